// round 14
// baseline (speedup 1.0000x reference)
#include <cuda_runtime.h>
#include <cuda_bf16.h>
#include <cstdint>

#define Bv 8
#define Tv 2048
#define Cv 768
#define Hv 64
#define NCH 4        // max KV chunks per 128-row query block (32 key-tiles / 8)
#define CHT 8        // key-tiles per chunk
#define LDK 72       // bf16 row stride (144B): ldmatrix conflict-free

// ---- scratch (__device__ globals) ----
__device__ __nv_bfloat16 g_qh[Bv * Tv * Hv];
__device__ __nv_bfloat16 g_ql[Bv * Tv * Hv];
__device__ float g_pacc[Bv * 16 * NCH * 128 * 64];   // 16.8 MB
__device__ float g_pml[Bv * 16 * NCH * 128 * 2];

// ============================ helpers =========================
__device__ __forceinline__ void mma16816(float* c, const uint32_t* a, uint32_t b0, uint32_t b1) {
    asm volatile(
        "mma.sync.aligned.m16n8k16.row.col.f32.bf16.bf16.f32 "
        "{%0,%1,%2,%3}, {%4,%5,%6,%7}, {%8,%9}, {%0,%1,%2,%3};"
        : "+f"(c[0]), "+f"(c[1]), "+f"(c[2]), "+f"(c[3])
        : "r"(a[0]), "r"(a[1]), "r"(a[2]), "r"(a[3]), "r"(b0), "r"(b1));
}
__device__ __forceinline__ void ldsm4(uint32_t addr, uint32_t& r0, uint32_t& r1,
                                      uint32_t& r2, uint32_t& r3) {
    asm volatile("ldmatrix.sync.aligned.m8n8.x4.shared.b16 {%0,%1,%2,%3}, [%4];"
                 : "=r"(r0), "=r"(r1), "=r"(r2), "=r"(r3) : "r"(addr));
}
__device__ __forceinline__ void ldsm4t(uint32_t addr, uint32_t& r0, uint32_t& r1,
                                       uint32_t& r2, uint32_t& r3) {
    asm volatile("ldmatrix.sync.aligned.m8n8.x4.trans.shared.b16 {%0,%1,%2,%3}, [%4];"
                 : "=r"(r0), "=r"(r1), "=r"(r2), "=r"(r3) : "r"(addr));
}
__device__ __forceinline__ uint32_t pack_bf16(float lo, float hi) {
    __nv_bfloat162 h = __floats2bfloat162_rn(lo, hi);
    return *reinterpret_cast<uint32_t*>(&h);
}
__device__ __forceinline__ void split4(float4 v, uint2& hi, uint2& lo) {
    __nv_bfloat162 ha = __floats2bfloat162_rn(v.x, v.y);
    __nv_bfloat162 hb = __floats2bfloat162_rn(v.z, v.w);
    __nv_bfloat162 la = __floats2bfloat162_rn(v.x - __bfloat162float(ha.x),
                                              v.y - __bfloat162float(ha.y));
    __nv_bfloat162 lb = __floats2bfloat162_rn(v.z - __bfloat162float(hb.x),
                                              v.w - __bfloat162float(hb.y));
    hi = make_uint2(*reinterpret_cast<uint32_t*>(&ha), *reinterpret_cast<uint32_t*>(&hb));
    lo = make_uint2(*reinterpret_cast<uint32_t*>(&la), *reinterpret_cast<uint32_t*>(&lb));
}
__device__ __forceinline__ void split2(float a, float b, uint32_t& hi, uint32_t& lo) {
    hi = pack_bf16(a, b);
    const __nv_bfloat162 h = *reinterpret_cast<const __nv_bfloat162*>(&hi);
    lo = pack_bf16(a - __bfloat162float(h.x), b - __bfloat162float(h.y));
}
__device__ __forceinline__ void cpa16(uint32_t dst, const void* src) {
    asm volatile("cp.async.ca.shared.global [%0], [%1], 16;" :: "r"(dst), "l"(src));
}

// ---------------------------------------------------------------------------
// Kernel 1: tensor-core q-projection, 64-row CTAs (exact R12 version, 24.2us).
// ---------------------------------------------------------------------------
__global__ __launch_bounds__(256, 2) void qproj_tc(const float* __restrict__ x,
                                                   const float* __restrict__ Wq) {
    extern __shared__ char smc[];
    __nv_bfloat16* Xhi = (__nv_bfloat16*)smc;            // 64*LDK
    __nv_bfloat16* Xlo = Xhi + 64 * LDK;
    __nv_bfloat16* Whi = Xlo + 64 * LDK;                 // 64*LDK
    __nv_bfloat16* Wlo = Whi + 64 * LDK;

    const int t = threadIdx.x;
    const int w = t >> 5, l = t & 31;
    const int gid = l >> 2, tig = l & 3;
    const int rg = w & 3;          // row-group (16 rows)
    const int nh = w >> 2;         // n-half (32 cols)
    const int row0 = blockIdx.x * 64;

    const int patA_row = l & 15;
    const int patA_col = (l >> 1) & 8;

    const uint32_t XhiB = (uint32_t)__cvta_generic_to_shared(Xhi);
    const uint32_t XloB = (uint32_t)__cvta_generic_to_shared(Xlo);
    const uint32_t WhiB = (uint32_t)__cvta_generic_to_shared(Whi);
    const uint32_t WloB = (uint32_t)__cvta_generic_to_shared(Wlo);

    float o[4][4];
#pragma unroll
    for (int nb = 0; nb < 4; nb++)
#pragma unroll
        for (int c = 0; c < 4; c++) o[nb][c] = 0.f;

    float4 px[4], pw[4];
#pragma unroll
    for (int i = 0; i < 4; i++) {
        const int idx4 = t + i * 256;
        const int r = idx4 >> 4, c4 = idx4 & 15;
        px[i] = *(const float4*)(x + (size_t)(row0 + r) * Cv + 4 * c4);
        pw[i] = *(const float4*)(Wq + (size_t)r * Hv + 4 * c4);
    }

    for (int kk = 0; kk < Cv; kk += 64) {
        __syncthreads();
#pragma unroll
        for (int i = 0; i < 4; i++) {
            const int idx4 = t + i * 256;
            const int r = idx4 >> 4, c4 = idx4 & 15;
            uint2 hi, lo;
            split4(px[i], hi, lo);
            *(uint2*)(Xhi + r * LDK + 4 * c4) = hi;
            *(uint2*)(Xlo + r * LDK + 4 * c4) = lo;
            split4(pw[i], hi, lo);
            *(uint2*)(Whi + r * LDK + 4 * c4) = hi;
            *(uint2*)(Wlo + r * LDK + 4 * c4) = lo;
        }
        if (kk + 64 < Cv) {
#pragma unroll
            for (int i = 0; i < 4; i++) {
                const int idx4 = t + i * 256;
                const int r = idx4 >> 4, c4 = idx4 & 15;
                px[i] = *(const float4*)(x + (size_t)(row0 + r) * Cv + kk + 64 + 4 * c4);
                pw[i] = *(const float4*)(Wq + (size_t)(kk + 64 + r) * Hv + 4 * c4);
            }
        }
        __syncthreads();

#pragma unroll
        for (int ks = 0; ks < 4; ks++) {
            uint32_t ah[4], al[4];
            const uint32_t aoff = (uint32_t)(((rg * 16 + patA_row) * LDK + ks * 16 + patA_col) * 2);
            ldsm4(XhiB + aoff, ah[0], ah[1], ah[2], ah[3]);
            ldsm4(XloB + aoff, al[0], al[1], al[2], al[3]);
#pragma unroll
            for (int nb2 = 0; nb2 < 2; nb2++) {
                const uint32_t boff =
                    (uint32_t)(((ks * 16 + patA_row) * LDK + nh * 32 + nb2 * 16 + patA_col) * 2);
                uint32_t vh0, vh1, vh2, vh3, vl0, vl1, vl2, vl3;
                ldsm4t(WhiB + boff, vh0, vh1, vh2, vh3);
                ldsm4t(WloB + boff, vl0, vl1, vl2, vl3);
                mma16816(o[2 * nb2],     ah, vh0, vh1);
                mma16816(o[2 * nb2],     ah, vl0, vl1);
                mma16816(o[2 * nb2],     al, vh0, vh1);
                mma16816(o[2 * nb2 + 1], ah, vh2, vh3);
                mma16816(o[2 * nb2 + 1], ah, vl2, vl3);
                mma16816(o[2 * nb2 + 1], al, vh2, vh3);
            }
        }
    }

    const int rl0 = rg * 16 + gid, rl1 = rl0 + 8;
#pragma unroll
    for (int nb = 0; nb < 4; nb++) {
        const int col = nh * 32 + nb * 8 + 2 * tig;
        uint32_t hb, lb;
        split2(o[nb][0], o[nb][1], hb, lb);
        *(uint32_t*)&g_qh[(size_t)(row0 + rl0) * Hv + col] = hb;
        *(uint32_t*)&g_ql[(size_t)(row0 + rl0) * Hv + col] = lb;
        split2(o[nb][2], o[nb][3], hb, lb);
        *(uint32_t*)&g_qh[(size_t)(row0 + rl1) * Hv + col] = hb;
        *(uint32_t*)&g_ql[(size_t)(row0 + rl1) * Hv + col] = lb;
    }
}

// ---------------------------------------------------------------------------
// Kernel 2: attention chunk (R12 version, 2 CTAs/SM; CHT=8 now).
// ---------------------------------------------------------------------------
__global__ __launch_bounds__(256, 2) void attn_chunk(const float* __restrict__ rel) {
    extern __shared__ char smc[];
    __nv_bfloat16* Qhi = (__nv_bfloat16*)smc;                 // 128*LDK
    __nv_bfloat16* Qlo = Qhi + 128 * LDK;
    __nv_bfloat16* Kbuf = Qlo + 128 * LDK;                    // 2 x (Khi + Klo) 64*LDK
    float* bias_s = (float*)(Kbuf + 2 * 2 * 64 * LDK);        // 192 floats

    const int qb = blockIdx.x;
    const int b  = blockIdx.y;
    const int ch = blockIdx.z;
    const int nkt = 2 * qb + 2;
    const int nch = (nkt + CHT - 1) / CHT;
    if (ch >= nch) return;

    const int t = threadIdx.x;
    const int w = t >> 5, l = t & 31;
    const int gid = l >> 2, tig = l & 3;
    const __nv_bfloat16* qh_base = g_qh + (size_t)b * Tv * Hv;
    const __nv_bfloat16* ql_base = g_ql + (size_t)b * Tv * Hv;

#pragma unroll
    for (int i = 0; i < 4; i++) {
        const int idx = t + i * 256;
        const int r = idx >> 3, c8 = idx & 7;
        *(uint4*)(Qhi + r * LDK + c8 * 8) =
            *(const uint4*)(qh_base + (size_t)(qb * 128 + r) * Hv + c8 * 8);
        *(uint4*)(Qlo + r * LDK + c8 * 8) =
            *(const uint4*)(ql_base + (size_t)(qb * 128 + r) * Hv + c8 * 8);
    }
    __syncthreads();

    const int patA_row = l & 15;
    const int patA_col = (l >> 1) & 8;
    const int patB_row = (l & 7) | ((l >> 1) & 8);
    const int patB_col = l & 8;

    const uint32_t QhiB = (uint32_t)__cvta_generic_to_shared(Qhi);
    const uint32_t QloB = (uint32_t)__cvta_generic_to_shared(Qlo);
    const uint32_t KB   = (uint32_t)__cvta_generic_to_shared(Kbuf);
    const uint32_t KBLK = (uint32_t)(2 * 64 * LDK * 2);
    const uint32_t KLO  = (uint32_t)(64 * LDK * 2);

    float o[8][4];
#pragma unroll
    for (int nb = 0; nb < 8; nb++)
#pragma unroll
        for (int c = 0; c < 4; c++) o[nb][c] = 0.f;
    float m0 = -1e30f, m1 = -1e30f, l0 = 0.f, l1 = 0.f;

    const int rl0 = w * 16 + gid, rl1 = rl0 + 8;
    const int qrow0 = qb * 128 + rl0;
    const int kt0 = ch * CHT;
    const int kt1 = min(kt0 + CHT - 1, nkt - 1);

    auto issue_k = [&](int kt, int buf) {
        const __nv_bfloat16* sh = qh_base + (size_t)(kt * 64) * Hv;
        const __nv_bfloat16* sl = ql_base + (size_t)(kt * 64) * Hv;
        const uint32_t dh = KB + (uint32_t)buf * KBLK;
#pragma unroll
        for (int i = 0; i < 2; i++) {
            const int idx = t + i * 256;
            const int r = idx >> 3, c8 = idx & 7;
            const uint32_t so = (uint32_t)((r * LDK + c8 * 8) * 2);
            cpa16(dh + so,       sh + r * Hv + c8 * 8);
            cpa16(dh + KLO + so, sl + r * Hv + c8 * 8);
        }
        asm volatile("cp.async.commit_group;");
    };

    issue_k(kt0, 0);

    for (int kt = kt0; kt <= kt1; kt++) {
        const int buf = (kt - kt0) & 1;
        __syncthreads();
        if (t < 192) bias_s[t] = rel[kt * 64 - qb * 128 + 1920 + t];
        if (kt < kt1) {
            issue_k(kt + 1, buf ^ 1);
            asm volatile("cp.async.wait_group 1;");
        } else {
            asm volatile("cp.async.wait_group 0;");
        }
        __syncthreads();

        const uint32_t KhiC = KB + (uint32_t)buf * KBLK;
        const uint32_t KloC = KhiC + KLO;

        float sc[8][4];
#pragma unroll
        for (int nb = 0; nb < 8; nb++)
#pragma unroll
            for (int c = 0; c < 4; c++) sc[nb][c] = 0.f;

#pragma unroll
        for (int ks = 0; ks < 4; ks++) {
            uint32_t qhf[4], qlf[4];
            const uint32_t qoff =
                (uint32_t)(((w * 16 + patA_row) * LDK + ks * 16 + patA_col) * 2);
            ldsm4(QhiB + qoff, qhf[0], qhf[1], qhf[2], qhf[3]);
            ldsm4(QloB + qoff, qlf[0], qlf[1], qlf[2], qlf[3]);
#pragma unroll
            for (int nb2 = 0; nb2 < 4; nb2++) {
                const uint32_t off =
                    (uint32_t)((((nb2 * 16) + patB_row) * LDK + ks * 16 + patB_col) * 2);
                uint32_t bh0, bh1, bh2, bh3, bl0, bl1, bl2, bl3;
                ldsm4(KhiC + off, bh0, bh1, bh2, bh3);
                ldsm4(KloC + off, bl0, bl1, bl2, bl3);
                mma16816(sc[2 * nb2],     qhf, bh0, bh1);
                mma16816(sc[2 * nb2],     qhf, bl0, bl1);
                mma16816(sc[2 * nb2],     qlf, bh0, bh1);
                mma16816(sc[2 * nb2 + 1], qhf, bh2, bh3);
                mma16816(sc[2 * nb2 + 1], qhf, bl2, bl3);
                mma16816(sc[2 * nb2 + 1], qlf, bh2, bh3);
            }
        }

        float mx0 = -1e30f, mx1 = -1e30f;
#pragma unroll
        for (int nb = 0; nb < 8; nb++) {
            const int kl = nb * 8 + 2 * tig;
            const int key = kt * 64 + kl;
            float v0 = sc[nb][0] * 0.125f + bias_s[kl - rl0 + 127];
            float v1 = sc[nb][1] * 0.125f + bias_s[kl + 1 - rl0 + 127];
            float v2 = sc[nb][2] * 0.125f + bias_s[kl - rl1 + 127];
            float v3 = sc[nb][3] * 0.125f + bias_s[kl + 1 - rl1 + 127];
            if (key > qrow0)         v0 = -1e30f;
            if (key + 1 > qrow0)     v1 = -1e30f;
            if (key > qrow0 + 8)     v2 = -1e30f;
            if (key + 1 > qrow0 + 8) v3 = -1e30f;
            sc[nb][0] = v0; sc[nb][1] = v1; sc[nb][2] = v2; sc[nb][3] = v3;
            mx0 = fmaxf(mx0, fmaxf(v0, v1));
            mx1 = fmaxf(mx1, fmaxf(v2, v3));
        }
        mx0 = fmaxf(mx0, __shfl_xor_sync(0xffffffffu, mx0, 1));
        mx0 = fmaxf(mx0, __shfl_xor_sync(0xffffffffu, mx0, 2));
        mx1 = fmaxf(mx1, __shfl_xor_sync(0xffffffffu, mx1, 1));
        mx1 = fmaxf(mx1, __shfl_xor_sync(0xffffffffu, mx1, 2));

        const float mn0 = fmaxf(m0, mx0), mn1 = fmaxf(m1, mx1);
        const float al0 = __expf(m0 - mn0), al1 = __expf(m1 - mn1);
        m0 = mn0; m1 = mn1;

        float s0 = 0.f, s1 = 0.f;
#pragma unroll
        for (int nb = 0; nb < 8; nb++) {
            sc[nb][0] = __expf(sc[nb][0] - mn0);
            sc[nb][1] = __expf(sc[nb][1] - mn0);
            sc[nb][2] = __expf(sc[nb][2] - mn1);
            sc[nb][3] = __expf(sc[nb][3] - mn1);
            s0 += sc[nb][0] + sc[nb][1];
            s1 += sc[nb][2] + sc[nb][3];
        }
        s0 += __shfl_xor_sync(0xffffffffu, s0, 1);
        s0 += __shfl_xor_sync(0xffffffffu, s0, 2);
        s1 += __shfl_xor_sync(0xffffffffu, s1, 1);
        s1 += __shfl_xor_sync(0xffffffffu, s1, 2);
        l0 = l0 * al0 + s0;
        l1 = l1 * al1 + s1;
#pragma unroll
        for (int nb = 0; nb < 8; nb++) {
            o[nb][0] *= al0; o[nb][1] *= al0;
            o[nb][2] *= al1; o[nb][3] *= al1;
        }

        uint32_t pah[4][4], pal[4][4];
#pragma unroll
        for (int ks = 0; ks < 4; ks++) {
            const float* pa = sc[2 * ks];
            const float* pb = sc[2 * ks + 1];
            split2(pa[0], pa[1], pah[ks][0], pal[ks][0]);
            split2(pa[2], pa[3], pah[ks][1], pal[ks][1]);
            split2(pb[0], pb[1], pah[ks][2], pal[ks][2]);
            split2(pb[2], pb[3], pah[ks][3], pal[ks][3]);
        }

#pragma unroll
        for (int ks = 0; ks < 4; ks++) {
#pragma unroll
            for (int nb2 = 0; nb2 < 4; nb2++) {
                const uint32_t off =
                    (uint32_t)(((ks * 16 + patA_row) * LDK + nb2 * 16 + patA_col) * 2);
                uint32_t vh0, vh1, vh2, vh3, vl0, vl1, vl2, vl3;
                ldsm4t(KhiC + off, vh0, vh1, vh2, vh3);
                ldsm4t(KloC + off, vl0, vl1, vl2, vl3);
                mma16816(o[2 * nb2],     pah[ks], vh0, vh1);
                mma16816(o[2 * nb2],     pah[ks], vl0, vl1);
                mma16816(o[2 * nb2],     pal[ks], vh0, vh1);
                mma16816(o[2 * nb2 + 1], pah[ks], vh2, vh3);
                mma16816(o[2 * nb2 + 1], pah[ks], vl2, vl3);
                mma16816(o[2 * nb2 + 1], pal[ks], vh2, vh3);
            }
        }
    }

    const size_t slot = ((size_t)(b * 16 + qb) * NCH + ch);
    float* pacc = g_pacc + slot * (128 * 64);
#pragma unroll
    for (int nb = 0; nb < 8; nb++) {
        const int col = nb * 8 + 2 * tig;
        *(float2*)&pacc[rl0 * 64 + col] = make_float2(o[nb][0], o[nb][1]);
        *(float2*)&pacc[rl1 * 64 + col] = make_float2(o[nb][2], o[nb][3]);
    }
    if (tig == 0) {
        float* pml = g_pml + slot * 256;
        pml[rl0 * 2 + 0] = m0;  pml[rl0 * 2 + 1] = l0;
        pml[rl1 * 2 + 0] = m1;  pml[rl1 * 2 + 1] = l1;
    }
}

// ---------------------------------------------------------------------------
// Kernel 3: combine chunk partials -> final output.
// ---------------------------------------------------------------------------
__global__ __launch_bounds__(256) void attn_combine(float* __restrict__ out) {
    __shared__ float ws[NCH][128];
    const int qb = blockIdx.x;
    const int b  = blockIdx.y;
    const int nch = (2 * qb + 2 + CHT - 1) / CHT;
    const int t = threadIdx.x;
    const size_t base = (size_t)(b * 16 + qb) * NCH;

    if (t < 128) {
        float mm[NCH], ll[NCH];
        float M = -1e30f;
        for (int c = 0; c < nch; c++) {
            mm[c] = g_pml[(base + c) * 256 + t * 2 + 0];
            ll[c] = g_pml[(base + c) * 256 + t * 2 + 1];
            M = fmaxf(M, mm[c]);
        }
        float L = 0.f;
        for (int c = 0; c < nch; c++) L += __expf(mm[c] - M) * ll[c];
        const float inv = 1.f / L;
        for (int c = 0; c < nch; c++) ws[c][t] = __expf(mm[c] - M) * inv;
    }
    __syncthreads();

    const float4* pacc4 = (const float4*)g_pacc;
    float4* out4 = (float4*)(out + ((size_t)b * Tv + qb * 128) * Hv);
    const int idx4 = blockIdx.z * 256 + t;
    const int r = idx4 >> 4;
    float4 s = make_float4(0.f, 0.f, 0.f, 0.f);
    for (int c = 0; c < nch; c++) {
        const float4 pv = pacc4[(base + c) * 2048 + idx4];
        const float wgt = ws[c][r];
        s.x += pv.x * wgt;  s.y += pv.y * wgt;
        s.z += pv.z * wgt;  s.w += pv.w * wgt;
    }
    out4[idx4] = s;
}

// ---------------------------------------------------------------------------
extern "C" void kernel_launch(void* const* d_in, const int* in_sizes, int n_in,
                              void* d_out, int out_size) {
    const float* x   = (const float*)d_in[0];
    const float* Wq  = (const float*)d_in[1];
    const float* rel = (const float*)d_in[2];
    float* out = (float*)d_out;

    const int qp_smem = 4 * 64 * LDK * 2;                              // 36864
    const int at_smem = (2 * 128 * LDK + 2 * 2 * 64 * LDK) * 2 + 768;  // 74496
    cudaFuncSetAttribute(qproj_tc,  cudaFuncAttributeMaxDynamicSharedMemorySize, qp_smem);
    cudaFuncSetAttribute(attn_chunk, cudaFuncAttributeMaxDynamicSharedMemorySize, at_smem);

    qproj_tc<<<Bv * Tv / 64, 256, qp_smem>>>(x, Wq);
    attn_chunk<<<dim3(16, Bv, NCH), 256, at_smem>>>(rel);
    attn_combine<<<dim3(16, Bv, 8), 256>>>(out);
}

// round 16
// speedup vs baseline: 1.0813x; 1.0813x over previous
#include <cuda_runtime.h>
#include <cuda_bf16.h>
#include <cstdint>

#define Bv 8
#define Tv 2048
#define Cv 768
#define Hv 64
#define NCH 8        // max KV chunks per 128-row query block (32 key-tiles / 4)
#define CHT 4        // key-tiles per chunk
#define LDK 72       // bf16 row stride (144B): ldmatrix conflict-free

// ---- scratch (__device__ globals) ----
__device__ __nv_bfloat16 g_wh[Cv * Hv];              // Wq hi plane
__device__ __nv_bfloat16 g_wl[Cv * Hv];              // Wq lo plane
__device__ __nv_bfloat16 g_qh[Bv * Tv * Hv];
__device__ __nv_bfloat16 g_ql[Bv * Tv * Hv];
__device__ float g_pacc[Bv * 16 * NCH * 128 * 64];   // 33.5 MB
__device__ float g_pml[Bv * 16 * NCH * 128 * 2];

// ============================ helpers =========================
__device__ __forceinline__ void mma16816(float* c, const uint32_t* a, uint32_t b0, uint32_t b1) {
    asm volatile(
        "mma.sync.aligned.m16n8k16.row.col.f32.bf16.bf16.f32 "
        "{%0,%1,%2,%3}, {%4,%5,%6,%7}, {%8,%9}, {%0,%1,%2,%3};"
        : "+f"(c[0]), "+f"(c[1]), "+f"(c[2]), "+f"(c[3])
        : "r"(a[0]), "r"(a[1]), "r"(a[2]), "r"(a[3]), "r"(b0), "r"(b1));
}
__device__ __forceinline__ void ldsm4(uint32_t addr, uint32_t& r0, uint32_t& r1,
                                      uint32_t& r2, uint32_t& r3) {
    asm volatile("ldmatrix.sync.aligned.m8n8.x4.shared.b16 {%0,%1,%2,%3}, [%4];"
                 : "=r"(r0), "=r"(r1), "=r"(r2), "=r"(r3) : "r"(addr));
}
__device__ __forceinline__ void ldsm4t(uint32_t addr, uint32_t& r0, uint32_t& r1,
                                       uint32_t& r2, uint32_t& r3) {
    asm volatile("ldmatrix.sync.aligned.m8n8.x4.trans.shared.b16 {%0,%1,%2,%3}, [%4];"
                 : "=r"(r0), "=r"(r1), "=r"(r2), "=r"(r3) : "r"(addr));
}
__device__ __forceinline__ uint32_t pack_bf16(float lo, float hi) {
    __nv_bfloat162 h = __floats2bfloat162_rn(lo, hi);
    return *reinterpret_cast<uint32_t*>(&h);
}
__device__ __forceinline__ void split4(float4 v, uint2& hi, uint2& lo) {
    __nv_bfloat162 ha = __floats2bfloat162_rn(v.x, v.y);
    __nv_bfloat162 hb = __floats2bfloat162_rn(v.z, v.w);
    __nv_bfloat162 la = __floats2bfloat162_rn(v.x - __bfloat162float(ha.x),
                                              v.y - __bfloat162float(ha.y));
    __nv_bfloat162 lb = __floats2bfloat162_rn(v.z - __bfloat162float(hb.x),
                                              v.w - __bfloat162float(hb.y));
    hi = make_uint2(*reinterpret_cast<uint32_t*>(&ha), *reinterpret_cast<uint32_t*>(&hb));
    lo = make_uint2(*reinterpret_cast<uint32_t*>(&la), *reinterpret_cast<uint32_t*>(&lb));
}
__device__ __forceinline__ void split2(float a, float b, uint32_t& hi, uint32_t& lo) {
    hi = pack_bf16(a, b);
    const __nv_bfloat162 h = *reinterpret_cast<const __nv_bfloat162*>(&hi);
    lo = pack_bf16(a - __bfloat162float(h.x), b - __bfloat162float(h.y));
}
__device__ __forceinline__ void cpa16(uint32_t dst, const void* src) {
    asm volatile("cp.async.ca.shared.global [%0], [%1], 16;" :: "r"(dst), "l"(src));
}

// ---------------------------------------------------------------------------
// Kernel 0: split Wq -> bf16 hi/lo planes (one float4 per thread).
// ---------------------------------------------------------------------------
__global__ __launch_bounds__(256) void wsplit(const float* __restrict__ Wq) {
    const int i4 = blockIdx.x * 256 + threadIdx.x;     // 0..12287
    const float4 v = ((const float4*)Wq)[i4];
    uint2 hi, lo;
    split4(v, hi, lo);
    *(uint2*)&g_wh[i4 * 4] = hi;
    *(uint2*)&g_wl[i4 * 4] = lo;
}

// ---------------------------------------------------------------------------
// Kernel 1: tensor-core q-projection (R12 structure; W comes pre-split).
// ---------------------------------------------------------------------------
__global__ __launch_bounds__(256, 2) void qproj_tc(const float* __restrict__ x) {
    extern __shared__ char smc[];
    __nv_bfloat16* Xhi = (__nv_bfloat16*)smc;            // 64*LDK
    __nv_bfloat16* Xlo = Xhi + 64 * LDK;
    __nv_bfloat16* Whi = Xlo + 64 * LDK;                 // 64*LDK
    __nv_bfloat16* Wlo = Whi + 64 * LDK;

    const int t = threadIdx.x;
    const int w = t >> 5, l = t & 31;
    const int gid = l >> 2, tig = l & 3;
    const int rg = w & 3;          // row-group (16 rows)
    const int nh = w >> 2;         // n-half (32 cols)
    const int row0 = blockIdx.x * 64;

    const int patA_row = l & 15;
    const int patA_col = (l >> 1) & 8;

    const uint32_t XhiB = (uint32_t)__cvta_generic_to_shared(Xhi);
    const uint32_t XloB = (uint32_t)__cvta_generic_to_shared(Xlo);
    const uint32_t WhiB = (uint32_t)__cvta_generic_to_shared(Whi);
    const uint32_t WloB = (uint32_t)__cvta_generic_to_shared(Wlo);

    float o[4][4];
#pragma unroll
    for (int nb = 0; nb < 4; nb++)
#pragma unroll
        for (int c = 0; c < 4; c++) o[nb][c] = 0.f;

    float4 px[4];
    uint2 pwh[4], pwl[4];
#pragma unroll
    for (int i = 0; i < 4; i++) {
        const int idx4 = t + i * 256;
        const int r = idx4 >> 4, c4 = idx4 & 15;
        px[i] = *(const float4*)(x + (size_t)(row0 + r) * Cv + 4 * c4);
        pwh[i] = *(const uint2*)(g_wh + (size_t)r * Hv + 4 * c4);
        pwl[i] = *(const uint2*)(g_wl + (size_t)r * Hv + 4 * c4);
    }

    for (int kk = 0; kk < Cv; kk += 64) {
        __syncthreads();
#pragma unroll
        for (int i = 0; i < 4; i++) {
            const int idx4 = t + i * 256;
            const int r = idx4 >> 4, c4 = idx4 & 15;
            uint2 hi, lo;
            split4(px[i], hi, lo);
            *(uint2*)(Xhi + r * LDK + 4 * c4) = hi;
            *(uint2*)(Xlo + r * LDK + 4 * c4) = lo;
            *(uint2*)(Whi + r * LDK + 4 * c4) = pwh[i];
            *(uint2*)(Wlo + r * LDK + 4 * c4) = pwl[i];
        }
        if (kk + 64 < Cv) {
#pragma unroll
            for (int i = 0; i < 4; i++) {
                const int idx4 = t + i * 256;
                const int r = idx4 >> 4, c4 = idx4 & 15;
                px[i] = *(const float4*)(x + (size_t)(row0 + r) * Cv + kk + 64 + 4 * c4);
                pwh[i] = *(const uint2*)(g_wh + (size_t)(kk + 64 + r) * Hv + 4 * c4);
                pwl[i] = *(const uint2*)(g_wl + (size_t)(kk + 64 + r) * Hv + 4 * c4);
            }
        }
        __syncthreads();

#pragma unroll
        for (int ks = 0; ks < 4; ks++) {
            uint32_t ah[4], al[4];
            const uint32_t aoff = (uint32_t)(((rg * 16 + patA_row) * LDK + ks * 16 + patA_col) * 2);
            ldsm4(XhiB + aoff, ah[0], ah[1], ah[2], ah[3]);
            ldsm4(XloB + aoff, al[0], al[1], al[2], al[3]);
#pragma unroll
            for (int nb2 = 0; nb2 < 2; nb2++) {
                const uint32_t boff =
                    (uint32_t)(((ks * 16 + patA_row) * LDK + nh * 32 + nb2 * 16 + patA_col) * 2);
                uint32_t vh0, vh1, vh2, vh3, vl0, vl1, vl2, vl3;
                ldsm4t(WhiB + boff, vh0, vh1, vh2, vh3);
                ldsm4t(WloB + boff, vl0, vl1, vl2, vl3);
                mma16816(o[2 * nb2],     ah, vh0, vh1);
                mma16816(o[2 * nb2],     ah, vl0, vl1);
                mma16816(o[2 * nb2],     al, vh0, vh1);
                mma16816(o[2 * nb2 + 1], ah, vh2, vh3);
                mma16816(o[2 * nb2 + 1], ah, vl2, vl3);
                mma16816(o[2 * nb2 + 1], al, vh2, vh3);
            }
        }
    }

    const int rl0 = rg * 16 + gid, rl1 = rl0 + 8;
#pragma unroll
    for (int nb = 0; nb < 4; nb++) {
        const int col = nh * 32 + nb * 8 + 2 * tig;
        uint32_t hb, lb;
        split2(o[nb][0], o[nb][1], hb, lb);
        *(uint32_t*)&g_qh[(size_t)(row0 + rl0) * Hv + col] = hb;
        *(uint32_t*)&g_ql[(size_t)(row0 + rl0) * Hv + col] = lb;
        split2(o[nb][2], o[nb][3], hb, lb);
        *(uint32_t*)&g_qh[(size_t)(row0 + rl1) * Hv + col] = hb;
        *(uint32_t*)&g_ql[(size_t)(row0 + rl1) * Hv + col] = lb;
    }
}

// ---------------------------------------------------------------------------
// Kernel 2: attention chunk (exact R12 version: CHT=4, 2 CTAs/SM).
// ---------------------------------------------------------------------------
__global__ __launch_bounds__(256, 2) void attn_chunk(const float* __restrict__ rel) {
    extern __shared__ char smc[];
    __nv_bfloat16* Qhi = (__nv_bfloat16*)smc;                 // 128*LDK
    __nv_bfloat16* Qlo = Qhi + 128 * LDK;
    __nv_bfloat16* Kbuf = Qlo + 128 * LDK;                    // 2 x (Khi + Klo) 64*LDK
    float* bias_s = (float*)(Kbuf + 2 * 2 * 64 * LDK);        // 192 floats

    const int qb = blockIdx.x;
    const int b  = blockIdx.y;
    const int ch = blockIdx.z;
    const int nkt = 2 * qb + 2;
    const int nch = (nkt + CHT - 1) / CHT;
    if (ch >= nch) return;

    const int t = threadIdx.x;
    const int w = t >> 5, l = t & 31;
    const int gid = l >> 2, tig = l & 3;
    const __nv_bfloat16* qh_base = g_qh + (size_t)b * Tv * Hv;
    const __nv_bfloat16* ql_base = g_ql + (size_t)b * Tv * Hv;

#pragma unroll
    for (int i = 0; i < 4; i++) {
        const int idx = t + i * 256;
        const int r = idx >> 3, c8 = idx & 7;
        *(uint4*)(Qhi + r * LDK + c8 * 8) =
            *(const uint4*)(qh_base + (size_t)(qb * 128 + r) * Hv + c8 * 8);
        *(uint4*)(Qlo + r * LDK + c8 * 8) =
            *(const uint4*)(ql_base + (size_t)(qb * 128 + r) * Hv + c8 * 8);
    }
    __syncthreads();

    const int patA_row = l & 15;
    const int patA_col = (l >> 1) & 8;
    const int patB_row = (l & 7) | ((l >> 1) & 8);
    const int patB_col = l & 8;

    const uint32_t QhiB = (uint32_t)__cvta_generic_to_shared(Qhi);
    const uint32_t QloB = (uint32_t)__cvta_generic_to_shared(Qlo);
    const uint32_t KB   = (uint32_t)__cvta_generic_to_shared(Kbuf);
    const uint32_t KBLK = (uint32_t)(2 * 64 * LDK * 2);
    const uint32_t KLO  = (uint32_t)(64 * LDK * 2);

    float o[8][4];
#pragma unroll
    for (int nb = 0; nb < 8; nb++)
#pragma unroll
        for (int c = 0; c < 4; c++) o[nb][c] = 0.f;
    float m0 = -1e30f, m1 = -1e30f, l0 = 0.f, l1 = 0.f;

    const int rl0 = w * 16 + gid, rl1 = rl0 + 8;
    const int qrow0 = qb * 128 + rl0;
    const int kt0 = ch * CHT;
    const int kt1 = min(kt0 + CHT - 1, nkt - 1);

    auto issue_k = [&](int kt, int buf) {
        const __nv_bfloat16* sh = qh_base + (size_t)(kt * 64) * Hv;
        const __nv_bfloat16* sl = ql_base + (size_t)(kt * 64) * Hv;
        const uint32_t dh = KB + (uint32_t)buf * KBLK;
#pragma unroll
        for (int i = 0; i < 2; i++) {
            const int idx = t + i * 256;
            const int r = idx >> 3, c8 = idx & 7;
            const uint32_t so = (uint32_t)((r * LDK + c8 * 8) * 2);
            cpa16(dh + so,       sh + r * Hv + c8 * 8);
            cpa16(dh + KLO + so, sl + r * Hv + c8 * 8);
        }
        asm volatile("cp.async.commit_group;");
    };

    issue_k(kt0, 0);

    for (int kt = kt0; kt <= kt1; kt++) {
        const int buf = (kt - kt0) & 1;
        __syncthreads();
        if (t < 192) bias_s[t] = rel[kt * 64 - qb * 128 + 1920 + t];
        if (kt < kt1) {
            issue_k(kt + 1, buf ^ 1);
            asm volatile("cp.async.wait_group 1;");
        } else {
            asm volatile("cp.async.wait_group 0;");
        }
        __syncthreads();

        const uint32_t KhiC = KB + (uint32_t)buf * KBLK;
        const uint32_t KloC = KhiC + KLO;

        float sc[8][4];
#pragma unroll
        for (int nb = 0; nb < 8; nb++)
#pragma unroll
            for (int c = 0; c < 4; c++) sc[nb][c] = 0.f;

#pragma unroll
        for (int ks = 0; ks < 4; ks++) {
            uint32_t qhf[4], qlf[4];
            const uint32_t qoff =
                (uint32_t)(((w * 16 + patA_row) * LDK + ks * 16 + patA_col) * 2);
            ldsm4(QhiB + qoff, qhf[0], qhf[1], qhf[2], qhf[3]);
            ldsm4(QloB + qoff, qlf[0], qlf[1], qlf[2], qlf[3]);
#pragma unroll
            for (int nb2 = 0; nb2 < 4; nb2++) {
                const uint32_t off =
                    (uint32_t)((((nb2 * 16) + patB_row) * LDK + ks * 16 + patB_col) * 2);
                uint32_t bh0, bh1, bh2, bh3, bl0, bl1, bl2, bl3;
                ldsm4(KhiC + off, bh0, bh1, bh2, bh3);
                ldsm4(KloC + off, bl0, bl1, bl2, bl3);
                mma16816(sc[2 * nb2],     qhf, bh0, bh1);
                mma16816(sc[2 * nb2],     qhf, bl0, bl1);
                mma16816(sc[2 * nb2],     qlf, bh0, bh1);
                mma16816(sc[2 * nb2 + 1], qhf, bh2, bh3);
                mma16816(sc[2 * nb2 + 1], qhf, bl2, bl3);
                mma16816(sc[2 * nb2 + 1], qlf, bh2, bh3);
            }
        }

        float mx0 = -1e30f, mx1 = -1e30f;
#pragma unroll
        for (int nb = 0; nb < 8; nb++) {
            const int kl = nb * 8 + 2 * tig;
            const int key = kt * 64 + kl;
            float v0 = sc[nb][0] * 0.125f + bias_s[kl - rl0 + 127];
            float v1 = sc[nb][1] * 0.125f + bias_s[kl + 1 - rl0 + 127];
            float v2 = sc[nb][2] * 0.125f + bias_s[kl - rl1 + 127];
            float v3 = sc[nb][3] * 0.125f + bias_s[kl + 1 - rl1 + 127];
            if (key > qrow0)         v0 = -1e30f;
            if (key + 1 > qrow0)     v1 = -1e30f;
            if (key > qrow0 + 8)     v2 = -1e30f;
            if (key + 1 > qrow0 + 8) v3 = -1e30f;
            sc[nb][0] = v0; sc[nb][1] = v1; sc[nb][2] = v2; sc[nb][3] = v3;
            mx0 = fmaxf(mx0, fmaxf(v0, v1));
            mx1 = fmaxf(mx1, fmaxf(v2, v3));
        }
        mx0 = fmaxf(mx0, __shfl_xor_sync(0xffffffffu, mx0, 1));
        mx0 = fmaxf(mx0, __shfl_xor_sync(0xffffffffu, mx0, 2));
        mx1 = fmaxf(mx1, __shfl_xor_sync(0xffffffffu, mx1, 1));
        mx1 = fmaxf(mx1, __shfl_xor_sync(0xffffffffu, mx1, 2));

        const float mn0 = fmaxf(m0, mx0), mn1 = fmaxf(m1, mx1);
        const float al0 = __expf(m0 - mn0), al1 = __expf(m1 - mn1);
        m0 = mn0; m1 = mn1;

        float s0 = 0.f, s1 = 0.f;
#pragma unroll
        for (int nb = 0; nb < 8; nb++) {
            sc[nb][0] = __expf(sc[nb][0] - mn0);
            sc[nb][1] = __expf(sc[nb][1] - mn0);
            sc[nb][2] = __expf(sc[nb][2] - mn1);
            sc[nb][3] = __expf(sc[nb][3] - mn1);
            s0 += sc[nb][0] + sc[nb][1];
            s1 += sc[nb][2] + sc[nb][3];
        }
        s0 += __shfl_xor_sync(0xffffffffu, s0, 1);
        s0 += __shfl_xor_sync(0xffffffffu, s0, 2);
        s1 += __shfl_xor_sync(0xffffffffu, s1, 1);
        s1 += __shfl_xor_sync(0xffffffffu, s1, 2);
        l0 = l0 * al0 + s0;
        l1 = l1 * al1 + s1;
#pragma unroll
        for (int nb = 0; nb < 8; nb++) {
            o[nb][0] *= al0; o[nb][1] *= al0;
            o[nb][2] *= al1; o[nb][3] *= al1;
        }

        uint32_t pah[4][4], pal[4][4];
#pragma unroll
        for (int ks = 0; ks < 4; ks++) {
            const float* pa = sc[2 * ks];
            const float* pb = sc[2 * ks + 1];
            split2(pa[0], pa[1], pah[ks][0], pal[ks][0]);
            split2(pa[2], pa[3], pah[ks][1], pal[ks][1]);
            split2(pb[0], pb[1], pah[ks][2], pal[ks][2]);
            split2(pb[2], pb[3], pah[ks][3], pal[ks][3]);
        }

#pragma unroll
        for (int ks = 0; ks < 4; ks++) {
#pragma unroll
            for (int nb2 = 0; nb2 < 4; nb2++) {
                const uint32_t off =
                    (uint32_t)(((ks * 16 + patA_row) * LDK + nb2 * 16 + patA_col) * 2);
                uint32_t vh0, vh1, vh2, vh3, vl0, vl1, vl2, vl3;
                ldsm4t(KhiC + off, vh0, vh1, vh2, vh3);
                ldsm4t(KloC + off, vl0, vl1, vl2, vl3);
                mma16816(o[2 * nb2],     pah[ks], vh0, vh1);
                mma16816(o[2 * nb2],     pah[ks], vl0, vl1);
                mma16816(o[2 * nb2],     pal[ks], vh0, vh1);
                mma16816(o[2 * nb2 + 1], pah[ks], vh2, vh3);
                mma16816(o[2 * nb2 + 1], pah[ks], vl2, vl3);
                mma16816(o[2 * nb2 + 1], pal[ks], vh2, vh3);
            }
        }
    }

    const size_t slot = ((size_t)(b * 16 + qb) * NCH + ch);
    float* pacc = g_pacc + slot * (128 * 64);
#pragma unroll
    for (int nb = 0; nb < 8; nb++) {
        const int col = nb * 8 + 2 * tig;
        *(float2*)&pacc[rl0 * 64 + col] = make_float2(o[nb][0], o[nb][1]);
        *(float2*)&pacc[rl1 * 64 + col] = make_float2(o[nb][2], o[nb][3]);
    }
    if (tig == 0) {
        float* pml = g_pml + slot * 256;
        pml[rl0 * 2 + 0] = m0;  pml[rl0 * 2 + 1] = l0;
        pml[rl1 * 2 + 0] = m1;  pml[rl1 * 2 + 1] = l1;
    }
}

// ---------------------------------------------------------------------------
// Kernel 3: combine v2 — compile-time-unrolled predicated loads (MLP=8).
// ---------------------------------------------------------------------------
__global__ __launch_bounds__(256) void attn_combine(float* __restrict__ out) {
    __shared__ float ws[NCH][128];
    const int qb = blockIdx.x;
    const int b  = blockIdx.y;
    const int nch = (2 * qb + 2 + CHT - 1) / CHT;
    const int t = threadIdx.x;
    const size_t base = (size_t)(b * 16 + qb) * NCH;

    if (t < 128) {
        float M = -1e30f;
        float mm[NCH], ll[NCH];
#pragma unroll
        for (int c = 0; c < NCH; c++) {
            if (c < nch) {
                mm[c] = g_pml[(base + c) * 256 + t * 2 + 0];
                ll[c] = g_pml[(base + c) * 256 + t * 2 + 1];
                M = fmaxf(M, mm[c]);
            }
        }
        float L = 0.f;
#pragma unroll
        for (int c = 0; c < NCH; c++)
            if (c < nch) L += __expf(mm[c] - M) * ll[c];
        const float inv = 1.f / L;
#pragma unroll
        for (int c = 0; c < NCH; c++)
            ws[c][t] = (c < nch) ? __expf(mm[c] - M) * inv : 0.f;
    }
    __syncthreads();

    const float4* pacc4 = (const float4*)g_pacc;
    float4* out4 = (float4*)(out + ((size_t)b * Tv + qb * 128) * Hv);
    const int idx4 = blockIdx.z * 256 + t;
    const int r = idx4 >> 4;

    // predicated, fully unrolled loads -> 8 LDG.128 in flight
    float4 pv[NCH];
#pragma unroll
    for (int c = 0; c < NCH; c++)
        pv[c] = (c < nch) ? pacc4[(base + c) * 2048 + idx4]
                          : make_float4(0.f, 0.f, 0.f, 0.f);

    float4 s = make_float4(0.f, 0.f, 0.f, 0.f);
#pragma unroll
    for (int c = 0; c < NCH; c++) {
        const float wgt = ws[c][r];
        s.x += pv[c].x * wgt;  s.y += pv[c].y * wgt;
        s.z += pv[c].z * wgt;  s.w += pv[c].w * wgt;
    }
    out4[idx4] = s;
}

// ---------------------------------------------------------------------------
extern "C" void kernel_launch(void* const* d_in, const int* in_sizes, int n_in,
                              void* d_out, int out_size) {
    const float* x   = (const float*)d_in[0];
    const float* Wq  = (const float*)d_in[1];
    const float* rel = (const float*)d_in[2];
    float* out = (float*)d_out;

    const int qp_smem = 4 * 64 * LDK * 2;                              // 36864
    const int at_smem = (2 * 128 * LDK + 2 * 2 * 64 * LDK) * 2 + 768;  // 74496
    cudaFuncSetAttribute(qproj_tc,  cudaFuncAttributeMaxDynamicSharedMemorySize, qp_smem);
    cudaFuncSetAttribute(attn_chunk, cudaFuncAttributeMaxDynamicSharedMemorySize, at_smem);

    wsplit<<<Cv * Hv / 4 / 256, 256>>>(Wq);
    qproj_tc<<<Bv * Tv / 64, 256, qp_smem>>>(x);
    attn_chunk<<<dim3(16, Bv, NCH), 256, at_smem>>>(rel);
    attn_combine<<<dim3(16, Bv, 8), 256>>>(out);
}